// round 15
// baseline (speedup 1.0000x reference)
#include <cuda_runtime.h>
#include <cuda_bf16.h>
#include <float.h>
#include <stdint.h>

// Problem constants
#define BB   32
#define DD   256
#define HW   1024
#define NN   (BB*HW)       // 32768
#define KK   1024

#define ZQ_SIZE  (NN*DD)
#define IDX_OFF  ZQ_SIZE
#define LOSS_OFF (ZQ_SIZE + NN)

// GEMM tiling (mma.sync m16n8k16 bf16)
#define MT   128           // rows per CTA
#define NC   32            // codes per chunk (double-buffered)
#define NCH  (KK/NC)       // 32 chunks
#define KSP  (DD/16)       // 16 k-steps of 16
#define CAP  16            // smem candidate slots per row
#define EXT  48            // global spill slots per row
#define WINDOW 2.0e-3f

// ---------------- helpers ----------------
__device__ __forceinline__ void mma_bf16(float* d, uint32_t a0, uint32_t a1,
                                         uint32_t a2, uint32_t a3,
                                         uint32_t b0, uint32_t b1) {
    asm volatile(
        "mma.sync.aligned.m16n8k16.row.col.f32.bf16.bf16.f32 "
        "{%0,%1,%2,%3}, {%4,%5,%6,%7}, {%8,%9}, {%0,%1,%2,%3};"
        : "+f"(d[0]), "+f"(d[1]), "+f"(d[2]), "+f"(d[3])
        : "r"(a0), "r"(a1), "r"(a2), "r"(a3), "r"(b0), "r"(b1));
}
__device__ __forceinline__ uint32_t pack_bf16(float lo, float hi) {
    __nv_bfloat162 h = __floats2bfloat162_rn(lo, hi);   // lo -> .x (low 16)
    return *(uint32_t*)&h;
}
__device__ __forceinline__ int   fmap(float f)  { int i = __float_as_int(f); return i < 0 ? (i ^ 0x7FFFFFFF) : i; }
__device__ __forceinline__ float funmap(int i)  { return __int_as_float(i < 0 ? (i ^ 0x7FFFFFFF) : i); }
__device__ __forceinline__ uint32_t smem_u32(const void* p) {
    uint32_t a;
    asm("{ .reg .u64 t; cvta.to.shared.u64 t, %1; cvt.u32.u64 %0, t; }" : "=r"(a) : "l"(p));
    return a;
}
#define CPASYNC16(smaddr, gptr) \
    asm volatile("cp.async.ca.shared.global [%0], [%1], 16;" :: "r"(smaddr), "l"(gptr))
#define CPCOMMIT() asm volatile("cp.async.commit_group;")
#define CPWAIT0()  asm volatile("cp.async.wait_group 0;" ::: "memory")
#define CPWAIT1()  asm volatile("cp.async.wait_group 1;" ::: "memory")

// ---------------- scratch ----------------
__device__ float g_cbnorm[KK];
__device__ float g_znorm[NN];
__device__ float g_zt[(size_t)NN * DD];       // z transposed to [n][d] (fp32, exact)
__device__ uint4 g_cbw4[KK * KSP * 8 / 4];    // codebook bf16, 16KB-chunk-major interleaved
__device__ uint4 g_zbw4[(size_t)NN * KSP * 8 / 4];  // z bf16, CTA-major interleaved
__device__ int   g_idx[NN];
__device__ float g_partial[2048];
__device__ int   g_candk[(size_t)NN * CAP];
__device__ int   g_candk_ext[(size_t)NN * EXT];
__device__ int   g_cnum[NN];

// ---------------- kernel 1a: codebook norms + bf16 image (NC=32 chunks) ------
__global__ void cbnorm_cbw_kernel(const float* __restrict__ cb) {
    uint32_t* g_cbw = (uint32_t*)g_cbw4;
    const int k = blockIdx.x * 32 + threadIdx.x;
    const float4* row4 = (const float4*)(cb + (size_t)k * DD);
    uint32_t* dbase = g_cbw + (((size_t)(k >> 5) * KSP) * NC + (k & 31)) * 8;
    float acc = 0.f;
    #pragma unroll 8
    for (int k4 = 0; k4 < 64; k4++) {
        float4 v = row4[k4];
        acc = __fadd_rn(acc, __fmul_rn(v.x, v.x));
        acc = __fadd_rn(acc, __fmul_rn(v.y, v.y));
        acc = __fadd_rn(acc, __fmul_rn(v.z, v.z));
        acc = __fadd_rn(acc, __fmul_rn(v.w, v.w));
        int ks = k4 >> 2, q = k4 & 3;
        int pos0 = (q < 2) ? q * 4 : (q - 2) * 4 + 1;
        uint32_t* dst = dbase + (size_t)ks * NC * 8;
        dst[pos0]     = pack_bf16(v.x, v.y);
        dst[pos0 + 2] = pack_bf16(v.z, v.w);
    }
    g_cbnorm[k] = acc;
}

// ---------------- kernel 1b: z fused pass — transpose + bf16 image + znorm ----
__global__ void z_fused_kernel(const float* __restrict__ z) {
    __shared__ float tile[DD * 33];              // [d][row], pad 33
    const int t   = threadIdx.x;
    const int n0  = blockIdx.x * 32;
    const int b   = n0 >> 10;
    const int hw0 = n0 & 1023;

    {
        const int hw = t & 31, dr = t >> 5;
        #pragma unroll 4
        for (int it = 0; it < 32; it++) {
            int d = it * 8 + dr;
            tile[d * 33 + hw] = z[((size_t)((b << 8) + d) << 10) + hw0 + hw];
        }
    }
    __syncthreads();

    #pragma unroll 4
    for (int it = 0; it < 32; it++) {
        int i = it * 256 + t;
        int d = i & 255, row = i >> 8;
        g_zt[(size_t)(n0 + row) * DD + d] = tile[d * 33 + row];
    }

    {
        uint32_t* g_zbw = (uint32_t*)g_zbw4;
        #pragma unroll
        for (int it = 0; it < 8; it++) {
            int i4 = it * 256 + t;                // 32 rows x 64 k4
            int row = i4 >> 6, k4 = i4 & 63;
            int n = n0 + row;
            float vx = tile[(k4 * 4 + 0) * 33 + row];
            float vy = tile[(k4 * 4 + 1) * 33 + row];
            float vz = tile[(k4 * 4 + 2) * 33 + row];
            float vw = tile[(k4 * 4 + 3) * 33 + row];
            int ks = k4 >> 2, q = k4 & 3;
            int pos0 = (q < 2) ? q * 4 : (q - 2) * 4 + 1;
            uint32_t* dst = g_zbw + ((((size_t)(n >> 7) * KSP + ks) * MT + (n & 127)) << 3);
            dst[pos0]     = pack_bf16(vx, vy);
            dst[pos0 + 2] = pack_bf16(vz, vw);
        }
    }

    if (t < 32) {
        float acc = 0.f;
        #pragma unroll 8
        for (int d = 0; d < DD; d++) {
            float v = tile[d * 33 + t];
            acc = __fadd_rn(acc, __fmul_rn(v, v));
        }
        g_znorm[n0 + t] = acc;
    }
}

// ---------------- kernel 2: bf16 MMA GEMM + fused min + windowed candidates ----
// 256 threads / 8 warps: 4 M-warps x 2 N-warps (16 cols each), NC=32 chunks,
// DOUBLE-BUFFERED cp.async B stream (wait_group 1 overlap).
// smem u32: As[16384] | Bs[2][4096] | cn[1024] | smin[128] | scnt[128]
//           | sck[128*16] = 111.6 KB -> 2 CTA/SM
__global__ void __launch_bounds__(256, 2)
mma_cand_kernel() {
    extern __shared__ uint32_t smu[];
    uint32_t* As   = smu;                         // 16384 u32
    uint32_t* Bs0  = smu + 16384;                 // 2 x 4096 u32
    float*    cn   = (float*)(Bs0 + 2 * 4096);    // 1024
    int*      smin = (int*)(cn + KK);             // 128
    int*      scnt = smin + 128;                  // 128
    int*      sck  = scnt + 128;                  // 128*16

    const uint32_t sbase = smem_u32(smu);

    const int t    = threadIdx.x;
    const int lane = t & 31;
    const int wid  = t >> 5;
    const int wm   = wid & 3;            // 4 warps over M (32 rows)
    const int wn   = wid >> 2;           // 2 warps over N (16 cols each)
    const int g    = lane >> 2;
    const int tg   = lane & 3;
    const int n0   = blockIdx.x * MT;

    // group 0: A tile (64 KB) + B chunk 0 (16 KB)
    {
        const uint4* asrc = g_zbw4 + (size_t)blockIdx.x * 4096;
        #pragma unroll
        for (int r = 0; r < 16; r++) {
            int i = r * 256 + t;
            CPASYNC16(sbase + 16 * i, asrc + i);
        }
        const uint4* bsrc = g_cbw4;
        #pragma unroll
        for (int r = 0; r < 4; r++) {
            int i = r * 256 + t;
            CPASYNC16(sbase + (16384 + i * 4) * 4, bsrc + i);
        }
        CPCOMMIT();
    }
    for (int i = t; i < KK; i += 256) cn[i] = g_cbnorm[i];
    if (t < MT) { smin[t] = fmap(FLT_MAX); scnt[t] = 0; }

    float znr[2][2];
    #pragma unroll
    for (int mf = 0; mf < 2; mf++) {
        znr[mf][0] = g_znorm[n0 + wm * 32 + mf * 16 + g];
        znr[mf][1] = g_znorm[n0 + wm * 32 + mf * 16 + g + 8];
    }

    for (int c = 0; c < NCH; c++) {
        const int c0 = c * NC;

        // issue B chunk c+1 into the other buffer (safe: all threads passed
        // the previous iteration's barrier, so chunk c-1's reads are done)
        if (c + 1 < NCH) {
            const uint4* bsrc = g_cbw4 + (size_t)(c + 1) * 1024;
            uint32_t bdst = sbase + (16384 + ((c + 1) & 1) * 4096) * 4;
            #pragma unroll
            for (int r = 0; r < 4; r++) {
                int i = r * 256 + t;
                CPASYNC16(bdst + 16 * i, bsrc + i);
            }
            CPCOMMIT();
            CPWAIT1();     // all but newest group -> chunk c (and A) ready
        } else {
            CPWAIT0();
        }
        __syncthreads();

        const uint32_t* Bs = Bs0 + (c & 1) * 4096;

        float acc[2][2][4];
        #pragma unroll
        for (int mf = 0; mf < 2; mf++)
            #pragma unroll
            for (int nf = 0; nf < 2; nf++)
                #pragma unroll
                for (int e = 0; e < 4; e++) acc[mf][nf][e] = 0.f;

        #pragma unroll 4
        for (int ks = 0; ks < KSP; ks++) {
            uint2 alo[2], ahi[2];
            #pragma unroll
            for (int mf = 0; mf < 2; mf++) {
                int r = wm * 32 + mf * 16 + g;
                alo[mf] = *(const uint2*)(As + ((ks * MT + r) << 3) + 2 * tg);
                ahi[mf] = *(const uint2*)(As + ((ks * MT + r + 8) << 3) + 2 * tg);
            }
            uint2 bf[2];
            #pragma unroll
            for (int nf = 0; nf < 2; nf++) {
                int cc = wn * 16 + nf * 8 + g;
                bf[nf] = *(const uint2*)(Bs + ((ks * NC + cc) << 3) + 2 * tg);
            }
            #pragma unroll
            for (int mf = 0; mf < 2; mf++)
                #pragma unroll
                for (int nf = 0; nf < 2; nf++)
                    mma_bf16(acc[mf][nf], alo[mf].x, ahi[mf].x, alo[mf].y, ahi[mf].y,
                             bf[nf].x, bf[nf].y);
        }

        // phase 1: dt computed ONCE, cached; per-row min -> smem atomicMin
        float dt[2][2][4];
        float rmin[2][2] = {{FLT_MAX, FLT_MAX}, {FLT_MAX, FLT_MAX}};
        #pragma unroll
        for (int mf = 0; mf < 2; mf++)
            #pragma unroll
            for (int nf = 0; nf < 2; nf++) {
                int col0 = wn * 16 + nf * 8 + 2 * tg;
                float c0v = cn[c0 + col0], c1v = cn[c0 + col0 + 1];
                dt[mf][nf][0] = (znr[mf][0] + c0v) - 2.f * acc[mf][nf][0];
                dt[mf][nf][1] = (znr[mf][0] + c1v) - 2.f * acc[mf][nf][1];
                dt[mf][nf][2] = (znr[mf][1] + c0v) - 2.f * acc[mf][nf][2];
                dt[mf][nf][3] = (znr[mf][1] + c1v) - 2.f * acc[mf][nf][3];
                rmin[mf][0] = fminf(rmin[mf][0], fminf(dt[mf][nf][0], dt[mf][nf][1]));
                rmin[mf][1] = fminf(rmin[mf][1], fminf(dt[mf][nf][2], dt[mf][nf][3]));
            }
        #pragma unroll
        for (int mf = 0; mf < 2; mf++)
            #pragma unroll
            for (int rr = 0; rr < 2; rr++) {
                float m = rmin[mf][rr];
                m = fminf(m, __shfl_xor_sync(0xFFFFFFFFu, m, 1));
                m = fminf(m, __shfl_xor_sync(0xFFFFFFFFu, m, 2));
                rmin[mf][rr] = m;
            }
        if (tg == 0) {
            #pragma unroll
            for (int mf = 0; mf < 2; mf++) {
                atomicMin(&smin[wm * 32 + mf * 16 + g],     fmap(rmin[mf][0]));
                atomicMin(&smin[wm * 32 + mf * 16 + g + 8], fmap(rmin[mf][1]));
            }
        }
        // no barrier: stale smem min >= final min keeps admission sound

        // phase 2: windowed admission from cached dt
        #pragma unroll
        for (int mf = 0; mf < 2; mf++) {
            int r0 = wm * 32 + mf * 16 + g;
            int r1 = r0 + 8;
            float th0 = fminf(funmap(smin[r0]), rmin[mf][0]) + WINDOW;
            float th1 = fminf(funmap(smin[r1]), rmin[mf][1]) + WINDOW;
            #pragma unroll
            for (int nf = 0; nf < 2; nf++) {
                int col0 = wn * 16 + nf * 8 + 2 * tg;
                if (dt[mf][nf][0] <= th0) {
                    int p = atomicAdd(&scnt[r0], 1);
                    if (p < CAP) sck[r0 * CAP + p] = c0 + col0;
                    else if (p < CAP + EXT) g_candk_ext[(size_t)(n0 + r0) * EXT + (p - CAP)] = c0 + col0;
                }
                if (dt[mf][nf][1] <= th0) {
                    int p = atomicAdd(&scnt[r0], 1);
                    if (p < CAP) sck[r0 * CAP + p] = c0 + col0 + 1;
                    else if (p < CAP + EXT) g_candk_ext[(size_t)(n0 + r0) * EXT + (p - CAP)] = c0 + col0 + 1;
                }
                if (dt[mf][nf][2] <= th1) {
                    int p = atomicAdd(&scnt[r1], 1);
                    if (p < CAP) sck[r1 * CAP + p] = c0 + col0;
                    else if (p < CAP + EXT) g_candk_ext[(size_t)(n0 + r1) * EXT + (p - CAP)] = c0 + col0;
                }
                if (dt[mf][nf][3] <= th1) {
                    int p = atomicAdd(&scnt[r1], 1);
                    if (p < CAP) sck[r1 * CAP + p] = c0 + col0 + 1;
                    else if (p < CAP + EXT) g_candk_ext[(size_t)(n0 + r1) * EXT + (p - CAP)] = c0 + col0 + 1;
                }
            }
        }
        __syncthreads();   // chunk c reads done before buffer reuse at c+2
    }

    if (t < MT) {
        int cnt = scnt[t];
        g_cnum[n0 + t] = (cnt > CAP + EXT) ? 255 : cnt;
        int m = (cnt > CAP) ? CAP : cnt;
        for (int q = 0; q < m; q++)
            g_candk[(size_t)(n0 + t) * CAP + q] = sck[t * CAP + q];
    }
}

// ---------------- kernel 2b: finalize — exact rescore of all candidates ----
__global__ void finalize_kernel(const float* __restrict__ cb) {
    const int t = threadIdx.x, w = t >> 5, l = t & 31;
    const int n = blockIdx.x * 8 + w;

    const int cnum = g_cnum[n];
    const float zn = g_znorm[n];
    const float* zr = g_zt + (size_t)n * DD;
    float zv[8];
    #pragma unroll
    for (int j = 0; j < 8; j++) zv[j] = zr[l + 32 * j];

    float bd = FLT_MAX;
    int   bk = 0x7FFFFFFF;
    const int cmax = (cnum == 255) ? KK : cnum;
    for (int c = 0; c < cmax; c++) {
        int k;
        if (cnum == 255)  k = c;
        else if (c < CAP) k = g_candk[(size_t)n * CAP + c];
        else              k = g_candk_ext[(size_t)n * EXT + (c - CAP)];
        const float* er = cb + (size_t)k * DD;
        float s = 0.f;
        #pragma unroll
        for (int j = 0; j < 8; j++) s = fmaf(zv[j], er[l + 32 * j], s);
        #pragma unroll
        for (int off = 16; off; off >>= 1) s += __shfl_xor_sync(0xFFFFFFFFu, s, off);
        // reference rounding: RN( RN(zn + cn) - 2*dot )
        float dist = __fadd_rn(__fadd_rn(zn, g_cbnorm[k]), -2.0f * s);
        if (dist < bd || (dist == bd && k < bk)) { bd = dist; bk = k; }
    }
    if (l == 0) g_idx[n] = bk;
}

// ---------------- kernel 3: gather + zq_st + indices + loss partials ----------
#define GN 128
#define GD 32
__global__ void gather_kernel(const float* __restrict__ z,
                              const float* __restrict__ cb,
                              float* __restrict__ out,
                              int write_extra) {
    __shared__ int   sidx[GN];
    __shared__ float tile[GD][GN + 1];
    __shared__ float red[8];

    const int t   = threadIdx.x;
    const int n0  = blockIdx.x * GN;
    const int d0  = blockIdx.y * GD;
    const int b   = n0 >> 10;
    const int hw0 = n0 & 1023;

    if (t < GN) sidx[t] = g_idx[n0 + t];
    __syncthreads();

    const int w = t >> 5, l = t & 31;
    for (int nn = w; nn < GN; nn += 8)
        tile[l][nn] = cb[sidx[nn] * DD + d0 + l];
    __syncthreads();

    float lsum = 0.f;
    #pragma unroll
    for (int r = 0; r < (GD * GN) / 256; r++) {
        int i  = r * 256 + t;
        int dd = i >> 7;
        int n  = i & 127;
        int d  = d0 + dd;
        float q  = tile[dd][n];
        int   zi = ((b << 8) + d) * HW + hw0 + n;
        float zv = z[zi];
        float df = __fsub_rn(q, zv);
        out[zi] = __fadd_rn(zv, df);       // zq_st = zp + RN(zq - zp), bitwise
        lsum = fmaf(df, df, lsum);
    }

    #pragma unroll
    for (int off = 16; off; off >>= 1)
        lsum += __shfl_xor_sync(0xFFFFFFFFu, lsum, off);
    if (l == 0) red[w] = lsum;
    __syncthreads();
    if (t == 0) {
        float s = 0.f;
        #pragma unroll
        for (int i = 0; i < 8; i++) s += red[i];
        g_partial[blockIdx.y * gridDim.x + blockIdx.x] = s;
    }
    if (write_extra && blockIdx.y == 0 && t < GN)
        out[IDX_OFF + n0 + t] = (float)sidx[t];
}

// ---------------- kernel 4: finalize loss ----------------
__global__ void loss_kernel(float* __restrict__ out) {
    __shared__ float red[8];
    int t = threadIdx.x;
    float s = 0.f;
    #pragma unroll
    for (int i = 0; i < 8; i++)
        s += g_partial[t * 8 + i];
    #pragma unroll
    for (int off = 16; off; off >>= 1)
        s += __shfl_xor_sync(0xFFFFFFFFu, s, off);
    if ((t & 31) == 0) red[t >> 5] = s;
    __syncthreads();
    if (t == 0) {
        double tot = 0.0;
        #pragma unroll
        for (int i = 0; i < 8; i++) tot += (double)red[i];
        out[LOSS_OFF] = (float)(2.0 * tot / (double)ZQ_SIZE);
    }
}

// ---------------- launch ----------------
extern "C" void kernel_launch(void* const* d_in, const int* in_sizes, int n_in,
                              void* d_out, int out_size) {
    const float* z  = (const float*)d_in[0];
    const float* cb = (const float*)d_in[1];
    float* out = (float*)d_out;

    int write_extra = (out_size >= LOSS_OFF + 1) ? 1 : 0;

    z_fused_kernel<<<NN / 32, 256>>>(z);
    cbnorm_cbw_kernel<<<KK / 32, 32>>>(cb);

    // smem: As 64K + Bs 2x16K + cn 4K + smin/scnt 1K + sck 8K = 111.6 KB
    size_t smem = (16384 + 2 * 4096 + KK + 128 + 128 + 128 * CAP) * 4;
    cudaFuncSetAttribute(mma_cand_kernel,
                         cudaFuncAttributeMaxDynamicSharedMemorySize, (int)smem);
    mma_cand_kernel<<<NN / MT, 256, smem>>>();

    finalize_kernel<<<NN / 8, 256>>>(cb);

    gather_kernel<<<dim3(NN / GN, DD / GD), 256>>>(z, cb, out, write_extra);

    if (write_extra)
        loss_kernel<<<1, 256>>>(out);
}

// round 16
// speedup vs baseline: 1.1053x; 1.1053x over previous
#include <cuda_runtime.h>
#include <cuda_bf16.h>
#include <float.h>
#include <stdint.h>

// Problem constants
#define BB   32
#define DD   256
#define HW   1024
#define NN   (BB*HW)       // 32768
#define KK   1024

#define ZQ_SIZE  (NN*DD)
#define IDX_OFF  ZQ_SIZE
#define LOSS_OFF (ZQ_SIZE + NN)

// GEMM tiling (mma.sync m16n8k16 bf16)
#define MT   128           // rows per CTA
#define NC   64            // codes per chunk
#define NCH  (KK/NC)       // 16 chunks
#define KSP  (DD/16)       // 16 k-steps of 16
#define CAP  16            // smem candidate slots per row
#define EXT  48            // global spill slots per row
#define WINDOW 2.0e-3f

// ---------------- helpers ----------------
__device__ __forceinline__ void mma_bf16(float* d, uint32_t a0, uint32_t a1,
                                         uint32_t a2, uint32_t a3,
                                         uint32_t b0, uint32_t b1) {
    asm volatile(
        "mma.sync.aligned.m16n8k16.row.col.f32.bf16.bf16.f32 "
        "{%0,%1,%2,%3}, {%4,%5,%6,%7}, {%8,%9}, {%0,%1,%2,%3};"
        : "+f"(d[0]), "+f"(d[1]), "+f"(d[2]), "+f"(d[3])
        : "r"(a0), "r"(a1), "r"(a2), "r"(a3), "r"(b0), "r"(b1));
}
__device__ __forceinline__ uint32_t pack_bf16(float lo, float hi) {
    __nv_bfloat162 h = __floats2bfloat162_rn(lo, hi);   // lo -> .x (low 16)
    return *(uint32_t*)&h;
}
__device__ __forceinline__ int   fmap(float f)  { int i = __float_as_int(f); return i < 0 ? (i ^ 0x7FFFFFFF) : i; }
__device__ __forceinline__ float funmap(int i)  { return __int_as_float(i < 0 ? (i ^ 0x7FFFFFFF) : i); }
__device__ __forceinline__ uint32_t smem_u32(const void* p) {
    uint32_t a;
    asm("{ .reg .u64 t; cvta.to.shared.u64 t, %1; cvt.u32.u64 %0, t; }" : "=r"(a) : "l"(p));
    return a;
}
#define CPASYNC16(smaddr, gptr) \
    asm volatile("cp.async.ca.shared.global [%0], [%1], 16;" :: "r"(smaddr), "l"(gptr))
#define CPCOMMIT() asm volatile("cp.async.commit_group;")
#define CPWAIT0()  asm volatile("cp.async.wait_group 0;" ::: "memory")

// ---------------- scratch ----------------
__device__ float g_cbnorm[KK];
__device__ float g_znorm[NN];
__device__ float g_zt[(size_t)NN * DD];       // z transposed to [n][d] (fp32, exact)
__device__ uint4 g_cbw4[KK * KSP * 8 / 4];    // codebook bf16, chunk-major interleaved
__device__ uint4 g_zbw4[(size_t)NN * KSP * 8 / 4];  // z bf16, CTA-major interleaved
__device__ int   g_idx[NN];
__device__ float g_partial[2048];
__device__ int   g_candk[(size_t)NN * CAP];
__device__ int   g_candk_ext[(size_t)NN * EXT];
__device__ int   g_cnum[NN];

// ---------------- kernel 1a: codebook norms + bf16 image, fused --------------
__global__ void cbnorm_cbw_kernel(const float* __restrict__ cb) {
    uint32_t* g_cbw = (uint32_t*)g_cbw4;
    const int k = blockIdx.x * 32 + threadIdx.x;
    const float4* row4 = (const float4*)(cb + (size_t)k * DD);
    uint32_t* dbase = g_cbw + ((((size_t)(k >> 6)) * KSP) * NC + (k & 63)) * 8;
    float acc = 0.f;
    #pragma unroll 8
    for (int k4 = 0; k4 < 64; k4++) {
        float4 v = row4[k4];
        acc = __fadd_rn(acc, __fmul_rn(v.x, v.x));
        acc = __fadd_rn(acc, __fmul_rn(v.y, v.y));
        acc = __fadd_rn(acc, __fmul_rn(v.z, v.z));
        acc = __fadd_rn(acc, __fmul_rn(v.w, v.w));
        int ks = k4 >> 2, q = k4 & 3;
        int pos0 = (q < 2) ? q * 4 : (q - 2) * 4 + 1;
        uint32_t* dst = dbase + (size_t)ks * NC * 8;
        dst[pos0]     = pack_bf16(v.x, v.y);
        dst[pos0 + 2] = pack_bf16(v.z, v.w);
    }
    g_cbnorm[k] = acc;
}

// ---------------- kernel 1b: z fused pass — transpose + bf16 image + znorm ----
__global__ void z_fused_kernel(const float* __restrict__ z) {
    __shared__ float tile[DD * 33];              // [d][row], pad 33
    const int t   = threadIdx.x;
    const int n0  = blockIdx.x * 32;
    const int b   = n0 >> 10;
    const int hw0 = n0 & 1023;

    {
        const int hw = t & 31, dr = t >> 5;
        #pragma unroll 4
        for (int it = 0; it < 32; it++) {
            int d = it * 8 + dr;
            tile[d * 33 + hw] = z[((size_t)((b << 8) + d) << 10) + hw0 + hw];
        }
    }
    __syncthreads();

    #pragma unroll 4
    for (int it = 0; it < 32; it++) {
        int i = it * 256 + t;
        int d = i & 255, row = i >> 8;
        g_zt[(size_t)(n0 + row) * DD + d] = tile[d * 33 + row];
    }

    {
        uint32_t* g_zbw = (uint32_t*)g_zbw4;
        #pragma unroll
        for (int it = 0; it < 8; it++) {
            int i4 = it * 256 + t;                // 32 rows x 64 k4
            int row = i4 >> 6, k4 = i4 & 63;
            int n = n0 + row;
            float vx = tile[(k4 * 4 + 0) * 33 + row];
            float vy = tile[(k4 * 4 + 1) * 33 + row];
            float vz = tile[(k4 * 4 + 2) * 33 + row];
            float vw = tile[(k4 * 4 + 3) * 33 + row];
            int ks = k4 >> 2, q = k4 & 3;
            int pos0 = (q < 2) ? q * 4 : (q - 2) * 4 + 1;
            uint32_t* dst = g_zbw + ((((size_t)(n >> 7) * KSP + ks) * MT + (n & 127)) << 3);
            dst[pos0]     = pack_bf16(vx, vy);
            dst[pos0 + 2] = pack_bf16(vz, vw);
        }
    }

    if (t < 32) {
        float acc = 0.f;
        #pragma unroll 8
        for (int d = 0; d < DD; d++) {
            float v = tile[d * 33 + t];
            acc = __fadd_rn(acc, __fmul_rn(v, v));
        }
        g_znorm[n0 + t] = acc;
    }
}

// ---------------- kernel 2: bf16 MMA GEMM + fused min + windowed candidates ----
// R14 structure (NC=64, single buffer), plus: dt cached between phases, and
// early-out predicate around the admission blocks.
__global__ void __launch_bounds__(256, 2)
mma_cand_kernel() {
    extern __shared__ uint32_t smu[];
    uint32_t* As   = smu;                         // 16384 u32
    uint32_t* Bs   = smu + 16384;                 // 8192 u32
    float*    cn   = (float*)(Bs + 8192);         // 1024
    int*      smin = (int*)(cn + KK);             // 128
    int*      scnt = smin + 128;                  // 128
    int*      sck  = scnt + 128;                  // 128*16

    const uint32_t sbase = smem_u32(smu);
    const uint32_t bbase = sbase + 16384 * 4;

    const int t    = threadIdx.x;
    const int lane = t & 31;
    const int wid  = t >> 5;
    const int wm   = wid & 3;
    const int wn   = wid >> 2;
    const int g    = lane >> 2;
    const int tg   = lane & 3;
    const int n0   = blockIdx.x * MT;

    {
        const uint4* asrc = g_zbw4 + (size_t)blockIdx.x * 4096;
        #pragma unroll
        for (int r = 0; r < 16; r++) {
            int i = r * 256 + t;
            CPASYNC16(sbase + 16 * i, asrc + i);
        }
    }
    for (int i = t; i < KK; i += 256) cn[i] = g_cbnorm[i];
    if (t < MT) { smin[t] = fmap(FLT_MAX); scnt[t] = 0; }

    float znr[2][2];
    #pragma unroll
    for (int mf = 0; mf < 2; mf++) {
        znr[mf][0] = g_znorm[n0 + wm * 32 + mf * 16 + g];
        znr[mf][1] = g_znorm[n0 + wm * 32 + mf * 16 + g + 8];
    }

    for (int c = 0; c < NCH; c++) {
        const int c0 = c * NC;
        __syncthreads();

        {
            const uint4* bsrc = g_cbw4 + (size_t)c * 2048;
            #pragma unroll
            for (int r = 0; r < 8; r++) {
                int i = r * 256 + t;
                CPASYNC16(bbase + 16 * i, bsrc + i);
            }
        }
        CPCOMMIT();
        CPWAIT0();
        __syncthreads();

        float acc[2][4][4];
        #pragma unroll
        for (int mf = 0; mf < 2; mf++)
            #pragma unroll
            for (int nf = 0; nf < 4; nf++)
                #pragma unroll
                for (int e = 0; e < 4; e++) acc[mf][nf][e] = 0.f;

        #pragma unroll 4
        for (int ks = 0; ks < KSP; ks++) {
            uint2 alo[2], ahi[2];
            #pragma unroll
            for (int mf = 0; mf < 2; mf++) {
                int r = wm * 32 + mf * 16 + g;
                alo[mf] = *(const uint2*)(As + ((ks * MT + r) << 3) + 2 * tg);
                ahi[mf] = *(const uint2*)(As + ((ks * MT + r + 8) << 3) + 2 * tg);
            }
            uint2 bf[4];
            #pragma unroll
            for (int nf = 0; nf < 4; nf++) {
                int cc = wn * 32 + nf * 8 + g;
                bf[nf] = *(const uint2*)(Bs + ((ks * NC + cc) << 3) + 2 * tg);
            }
            #pragma unroll
            for (int mf = 0; mf < 2; mf++)
                #pragma unroll
                for (int nf = 0; nf < 4; nf++)
                    mma_bf16(acc[mf][nf], alo[mf].x, ahi[mf].x, alo[mf].y, ahi[mf].y,
                             bf[nf].x, bf[nf].y);
        }

        // phase 1: dt computed ONCE and cached; per-row min -> smem atomicMin
        float dt[2][4][4];
        float rmin[2][2] = {{FLT_MAX, FLT_MAX}, {FLT_MAX, FLT_MAX}};
        #pragma unroll
        for (int mf = 0; mf < 2; mf++)
            #pragma unroll
            for (int nf = 0; nf < 4; nf++) {
                int col0 = wn * 32 + nf * 8 + 2 * tg;
                float c0v = cn[c0 + col0], c1v = cn[c0 + col0 + 1];
                dt[mf][nf][0] = (znr[mf][0] + c0v) - 2.f * acc[mf][nf][0];
                dt[mf][nf][1] = (znr[mf][0] + c1v) - 2.f * acc[mf][nf][1];
                dt[mf][nf][2] = (znr[mf][1] + c0v) - 2.f * acc[mf][nf][2];
                dt[mf][nf][3] = (znr[mf][1] + c1v) - 2.f * acc[mf][nf][3];
                rmin[mf][0] = fminf(rmin[mf][0], fminf(dt[mf][nf][0], dt[mf][nf][1]));
                rmin[mf][1] = fminf(rmin[mf][1], fminf(dt[mf][nf][2], dt[mf][nf][3]));
            }
        #pragma unroll
        for (int mf = 0; mf < 2; mf++)
            #pragma unroll
            for (int rr = 0; rr < 2; rr++) {
                float m = rmin[mf][rr];
                m = fminf(m, __shfl_xor_sync(0xFFFFFFFFu, m, 1));
                m = fminf(m, __shfl_xor_sync(0xFFFFFFFFu, m, 2));
                rmin[mf][rr] = m;
            }
        if (tg == 0) {
            #pragma unroll
            for (int mf = 0; mf < 2; mf++) {
                atomicMin(&smin[wm * 32 + mf * 16 + g],     fmap(rmin[mf][0]));
                atomicMin(&smin[wm * 32 + mf * 16 + g + 8], fmap(rmin[mf][1]));
            }
        }
        // no barrier: stale smem min >= final min keeps admission sound

        // phase 2: windowed admission from cached dt, early-out when no hit
        #pragma unroll
        for (int mf = 0; mf < 2; mf++) {
            int r0 = wm * 32 + mf * 16 + g;
            int r1 = r0 + 8;
            float th0 = fminf(funmap(smin[r0]), rmin[mf][0]) + WINDOW;
            float th1 = fminf(funmap(smin[r1]), rmin[mf][1]) + WINDOW;
            float m0 = FLT_MAX, m1 = FLT_MAX;
            #pragma unroll
            for (int nf = 0; nf < 4; nf++) {
                m0 = fminf(m0, fminf(dt[mf][nf][0], dt[mf][nf][1]));
                m1 = fminf(m1, fminf(dt[mf][nf][2], dt[mf][nf][3]));
            }
            if (m0 <= th0) {
                #pragma unroll
                for (int nf = 0; nf < 4; nf++) {
                    int col0 = wn * 32 + nf * 8 + 2 * tg;
                    if (dt[mf][nf][0] <= th0) {
                        int p = atomicAdd(&scnt[r0], 1);
                        if (p < CAP) sck[r0 * CAP + p] = c0 + col0;
                        else if (p < CAP + EXT) g_candk_ext[(size_t)(n0 + r0) * EXT + (p - CAP)] = c0 + col0;
                    }
                    if (dt[mf][nf][1] <= th0) {
                        int p = atomicAdd(&scnt[r0], 1);
                        if (p < CAP) sck[r0 * CAP + p] = c0 + col0 + 1;
                        else if (p < CAP + EXT) g_candk_ext[(size_t)(n0 + r0) * EXT + (p - CAP)] = c0 + col0 + 1;
                    }
                }
            }
            if (m1 <= th1) {
                #pragma unroll
                for (int nf = 0; nf < 4; nf++) {
                    int col0 = wn * 32 + nf * 8 + 2 * tg;
                    if (dt[mf][nf][2] <= th1) {
                        int p = atomicAdd(&scnt[r1], 1);
                        if (p < CAP) sck[r1 * CAP + p] = c0 + col0;
                        else if (p < CAP + EXT) g_candk_ext[(size_t)(n0 + r1) * EXT + (p - CAP)] = c0 + col0;
                    }
                    if (dt[mf][nf][3] <= th1) {
                        int p = atomicAdd(&scnt[r1], 1);
                        if (p < CAP) sck[r1 * CAP + p] = c0 + col0 + 1;
                        else if (p < CAP + EXT) g_candk_ext[(size_t)(n0 + r1) * EXT + (p - CAP)] = c0 + col0 + 1;
                    }
                }
            }
        }
    }
    __syncthreads();

    if (t < MT) {
        int cnt = scnt[t];
        g_cnum[n0 + t] = (cnt > CAP + EXT) ? 255 : cnt;
        int m = (cnt > CAP) ? CAP : cnt;
        for (int q = 0; q < m; q++)
            g_candk[(size_t)(n0 + t) * CAP + q] = sck[t * CAP + q];
    }
}

// ---------------- kernel 2b: finalize — exact rescore of all candidates ----
__global__ void finalize_kernel(const float* __restrict__ cb) {
    const int t = threadIdx.x, w = t >> 5, l = t & 31;
    const int n = blockIdx.x * 8 + w;

    const int cnum = g_cnum[n];
    const float zn = g_znorm[n];
    const float* zr = g_zt + (size_t)n * DD;
    float zv[8];
    #pragma unroll
    for (int j = 0; j < 8; j++) zv[j] = zr[l + 32 * j];

    float bd = FLT_MAX;
    int   bk = 0x7FFFFFFF;
    const int cmax = (cnum == 255) ? KK : cnum;
    for (int c = 0; c < cmax; c++) {
        int k;
        if (cnum == 255)  k = c;
        else if (c < CAP) k = g_candk[(size_t)n * CAP + c];
        else              k = g_candk_ext[(size_t)n * EXT + (c - CAP)];
        const float* er = cb + (size_t)k * DD;
        float s = 0.f;
        #pragma unroll
        for (int j = 0; j < 8; j++) s = fmaf(zv[j], er[l + 32 * j], s);
        #pragma unroll
        for (int off = 16; off; off >>= 1) s += __shfl_xor_sync(0xFFFFFFFFu, s, off);
        // reference rounding: RN( RN(zn + cn) - 2*dot )
        float dist = __fadd_rn(__fadd_rn(zn, g_cbnorm[k]), -2.0f * s);
        if (dist < bd || (dist == bd && k < bk)) { bd = dist; bk = k; }
    }
    if (l == 0) g_idx[n] = bk;
}

// ---------------- kernel 3: gather + zq_st + indices + loss partials ----------
#define GN 128
#define GD 32
__global__ void gather_kernel(const float* __restrict__ z,
                              const float* __restrict__ cb,
                              float* __restrict__ out,
                              int write_extra) {
    __shared__ int   sidx[GN];
    __shared__ float tile[GD][GN + 1];
    __shared__ float red[8];

    const int t   = threadIdx.x;
    const int n0  = blockIdx.x * GN;
    const int d0  = blockIdx.y * GD;
    const int b   = n0 >> 10;
    const int hw0 = n0 & 1023;

    if (t < GN) sidx[t] = g_idx[n0 + t];
    __syncthreads();

    const int w = t >> 5, l = t & 31;
    for (int nn = w; nn < GN; nn += 8)
        tile[l][nn] = cb[sidx[nn] * DD + d0 + l];
    __syncthreads();

    float lsum = 0.f;
    #pragma unroll
    for (int r = 0; r < (GD * GN) / 256; r++) {
        int i  = r * 256 + t;
        int dd = i >> 7;
        int n  = i & 127;
        int d  = d0 + dd;
        float q  = tile[dd][n];
        int   zi = ((b << 8) + d) * HW + hw0 + n;
        float zv = z[zi];
        float df = __fsub_rn(q, zv);
        out[zi] = __fadd_rn(zv, df);       // zq_st = zp + RN(zq - zp), bitwise
        lsum = fmaf(df, df, lsum);
    }

    #pragma unroll
    for (int off = 16; off; off >>= 1)
        lsum += __shfl_xor_sync(0xFFFFFFFFu, lsum, off);
    if (l == 0) red[w] = lsum;
    __syncthreads();
    if (t == 0) {
        float s = 0.f;
        #pragma unroll
        for (int i = 0; i < 8; i++) s += red[i];
        g_partial[blockIdx.y * gridDim.x + blockIdx.x] = s;
    }
    if (write_extra && blockIdx.y == 0 && t < GN)
        out[IDX_OFF + n0 + t] = (float)sidx[t];
}

// ---------------- kernel 4: finalize loss ----------------
__global__ void loss_kernel(float* __restrict__ out) {
    __shared__ float red[8];
    int t = threadIdx.x;
    float s = 0.f;
    #pragma unroll
    for (int i = 0; i < 8; i++)
        s += g_partial[t * 8 + i];
    #pragma unroll
    for (int off = 16; off; off >>= 1)
        s += __shfl_xor_sync(0xFFFFFFFFu, s, off);
    if ((t & 31) == 0) red[t >> 5] = s;
    __syncthreads();
    if (t == 0) {
        double tot = 0.0;
        #pragma unroll
        for (int i = 0; i < 8; i++) tot += (double)red[i];
        out[LOSS_OFF] = (float)(2.0 * tot / (double)ZQ_SIZE);
    }
}

// ---------------- launch ----------------
extern "C" void kernel_launch(void* const* d_in, const int* in_sizes, int n_in,
                              void* d_out, int out_size) {
    const float* z  = (const float*)d_in[0];
    const float* cb = (const float*)d_in[1];
    float* out = (float*)d_out;

    int write_extra = (out_size >= LOSS_OFF + 1) ? 1 : 0;

    z_fused_kernel<<<NN / 32, 256>>>(z);
    cbnorm_cbw_kernel<<<KK / 32, 32>>>(cb);

    // smem: As 64K + Bs 32K + cn 4K + smin/scnt 1K + sck 8K = 109 KB
    size_t smem = (16384 + 8192 + KK + 128 + 128 + 128 * CAP) * 4;
    cudaFuncSetAttribute(mma_cand_kernel,
                         cudaFuncAttributeMaxDynamicSharedMemorySize, (int)smem);
    mma_cand_kernel<<<NN / MT, 256, smem>>>();

    finalize_kernel<<<NN / 8, 256>>>(cb);

    gather_kernel<<<dim3(NN / GN, DD / GD), 256>>>(z, cb, out, write_extra);

    if (write_extra)
        loss_kernel<<<1, 256>>>(out);
}

// round 17
// speedup vs baseline: 1.1330x; 1.0250x over previous
#include <cuda_runtime.h>
#include <cuda_bf16.h>
#include <float.h>
#include <stdint.h>

// Problem constants
#define BB   32
#define DD   256
#define HW   1024
#define NN   (BB*HW)       // 32768
#define KK   1024

#define ZQ_SIZE  (NN*DD)
#define IDX_OFF  ZQ_SIZE
#define LOSS_OFF (ZQ_SIZE + NN)

// GEMM tiling (mma.sync m16n8k16 bf16)
#define MT   128           // rows per CTA
#define NC   64            // codes per chunk
#define NCH  (KK/NC)       // 16 chunks
#define KSP  (DD/16)       // 16 k-steps of 16
#define CAP  16            // smem candidate slots per row
#define EXT  48            // global spill slots per row
#define WINDOW 2.0e-3f

// ---------------- helpers ----------------
__device__ __forceinline__ void mma_bf16(float* d, uint32_t a0, uint32_t a1,
                                         uint32_t a2, uint32_t a3,
                                         uint32_t b0, uint32_t b1) {
    asm volatile(
        "mma.sync.aligned.m16n8k16.row.col.f32.bf16.bf16.f32 "
        "{%0,%1,%2,%3}, {%4,%5,%6,%7}, {%8,%9}, {%0,%1,%2,%3};"
        : "+f"(d[0]), "+f"(d[1]), "+f"(d[2]), "+f"(d[3])
        : "r"(a0), "r"(a1), "r"(a2), "r"(a3), "r"(b0), "r"(b1));
}
__device__ __forceinline__ uint32_t pack_bf16(float lo, float hi) {
    __nv_bfloat162 h = __floats2bfloat162_rn(lo, hi);   // lo -> .x (low 16)
    return *(uint32_t*)&h;
}
__device__ __forceinline__ int   fmap(float f)  { int i = __float_as_int(f); return i < 0 ? (i ^ 0x7FFFFFFF) : i; }
__device__ __forceinline__ float funmap(int i)  { return __int_as_float(i < 0 ? (i ^ 0x7FFFFFFF) : i); }
__device__ __forceinline__ uint32_t smem_u32(const void* p) {
    uint32_t a;
    asm("{ .reg .u64 t; cvta.to.shared.u64 t, %1; cvt.u32.u64 %0, t; }" : "=r"(a) : "l"(p));
    return a;
}
#define CPASYNC16(smaddr, gptr) \
    asm volatile("cp.async.ca.shared.global [%0], [%1], 16;" :: "r"(smaddr), "l"(gptr))
#define CPCOMMIT() asm volatile("cp.async.commit_group;")
#define CPWAIT0()  asm volatile("cp.async.wait_group 0;" ::: "memory")

// ---------------- scratch ----------------
__device__ float g_cbnorm[KK];
__device__ float g_znorm[NN];
__device__ float g_zt[(size_t)NN * DD];       // z transposed to [n][d] (fp32, exact)
__device__ uint4 g_cbw4[KK * KSP * 8 / 4];    // codebook bf16, chunk-major interleaved
__device__ uint4 g_zbw4[(size_t)NN * KSP * 8 / 4];  // z bf16, CTA-major interleaved
__device__ int   g_idx[NN];
__device__ float g_partial[2048];
__device__ int   g_candk[(size_t)NN * CAP];
__device__ int   g_candk_ext[(size_t)NN * EXT];
__device__ int   g_cnum[NN];

// ---------------- kernel 1a: codebook norms + bf16 image, fused --------------
__global__ void cbnorm_cbw_kernel(const float* __restrict__ cb) {
    uint32_t* g_cbw = (uint32_t*)g_cbw4;
    const int k = blockIdx.x * 32 + threadIdx.x;
    const float4* row4 = (const float4*)(cb + (size_t)k * DD);
    uint32_t* dbase = g_cbw + ((((size_t)(k >> 6)) * KSP) * NC + (k & 63)) * 8;
    float acc = 0.f;
    #pragma unroll 8
    for (int k4 = 0; k4 < 64; k4++) {
        float4 v = row4[k4];
        acc = __fadd_rn(acc, __fmul_rn(v.x, v.x));
        acc = __fadd_rn(acc, __fmul_rn(v.y, v.y));
        acc = __fadd_rn(acc, __fmul_rn(v.z, v.z));
        acc = __fadd_rn(acc, __fmul_rn(v.w, v.w));
        int ks = k4 >> 2, q = k4 & 3;
        int pos0 = (q < 2) ? q * 4 : (q - 2) * 4 + 1;
        uint32_t* dst = dbase + (size_t)ks * NC * 8;
        dst[pos0]     = pack_bf16(v.x, v.y);
        dst[pos0 + 2] = pack_bf16(v.z, v.w);
    }
    g_cbnorm[k] = acc;
}

// ---------------- kernel 1b: z fused pass — transpose + bf16 image + znorm ----
__global__ void z_fused_kernel(const float* __restrict__ z) {
    __shared__ float tile[DD * 33];              // [d][row], pad 33
    const int t   = threadIdx.x;
    const int n0  = blockIdx.x * 32;
    const int b   = n0 >> 10;
    const int hw0 = n0 & 1023;

    {
        const int hw = t & 31, dr = t >> 5;
        #pragma unroll 4
        for (int it = 0; it < 32; it++) {
            int d = it * 8 + dr;
            tile[d * 33 + hw] = z[((size_t)((b << 8) + d) << 10) + hw0 + hw];
        }
    }
    __syncthreads();

    #pragma unroll 4
    for (int it = 0; it < 32; it++) {
        int i = it * 256 + t;
        int d = i & 255, row = i >> 8;
        g_zt[(size_t)(n0 + row) * DD + d] = tile[d * 33 + row];
    }

    {
        uint32_t* g_zbw = (uint32_t*)g_zbw4;
        #pragma unroll
        for (int it = 0; it < 8; it++) {
            int i4 = it * 256 + t;                // 32 rows x 64 k4
            int row = i4 >> 6, k4 = i4 & 63;
            int n = n0 + row;
            float vx = tile[(k4 * 4 + 0) * 33 + row];
            float vy = tile[(k4 * 4 + 1) * 33 + row];
            float vz = tile[(k4 * 4 + 2) * 33 + row];
            float vw = tile[(k4 * 4 + 3) * 33 + row];
            int ks = k4 >> 2, q = k4 & 3;
            int pos0 = (q < 2) ? q * 4 : (q - 2) * 4 + 1;
            uint32_t* dst = g_zbw + ((((size_t)(n >> 7) * KSP + ks) * MT + (n & 127)) << 3);
            dst[pos0]     = pack_bf16(vx, vy);
            dst[pos0 + 2] = pack_bf16(vz, vw);
        }
    }

    if (t < 32) {
        float acc = 0.f;
        #pragma unroll 8
        for (int d = 0; d < DD; d++) {
            float v = tile[d * 33 + t];
            acc = __fadd_rn(acc, __fmul_rn(v, v));
        }
        g_znorm[n0 + t] = acc;
    }
}

// ---------------- kernel 2: bf16 MMA GEMM + fused min + windowed candidates ----
// (byte-identical to the 159.8us R16 lineage)
__global__ void __launch_bounds__(256, 2)
mma_cand_kernel() {
    extern __shared__ uint32_t smu[];
    uint32_t* As   = smu;                         // 16384 u32
    uint32_t* Bs   = smu + 16384;                 // 8192 u32
    float*    cn   = (float*)(Bs + 8192);         // 1024
    int*      smin = (int*)(cn + KK);             // 128
    int*      scnt = smin + 128;                  // 128
    int*      sck  = scnt + 128;                  // 128*16

    const uint32_t sbase = smem_u32(smu);
    const uint32_t bbase = sbase + 16384 * 4;

    const int t    = threadIdx.x;
    const int lane = t & 31;
    const int wid  = t >> 5;
    const int wm   = wid & 3;
    const int wn   = wid >> 2;
    const int g    = lane >> 2;
    const int tg   = lane & 3;
    const int n0   = blockIdx.x * MT;

    {
        const uint4* asrc = g_zbw4 + (size_t)blockIdx.x * 4096;
        #pragma unroll
        for (int r = 0; r < 16; r++) {
            int i = r * 256 + t;
            CPASYNC16(sbase + 16 * i, asrc + i);
        }
    }
    for (int i = t; i < KK; i += 256) cn[i] = g_cbnorm[i];
    if (t < MT) { smin[t] = fmap(FLT_MAX); scnt[t] = 0; }

    float znr[2][2];
    #pragma unroll
    for (int mf = 0; mf < 2; mf++) {
        znr[mf][0] = g_znorm[n0 + wm * 32 + mf * 16 + g];
        znr[mf][1] = g_znorm[n0 + wm * 32 + mf * 16 + g + 8];
    }

    for (int c = 0; c < NCH; c++) {
        const int c0 = c * NC;
        __syncthreads();

        {
            const uint4* bsrc = g_cbw4 + (size_t)c * 2048;
            #pragma unroll
            for (int r = 0; r < 8; r++) {
                int i = r * 256 + t;
                CPASYNC16(bbase + 16 * i, bsrc + i);
            }
        }
        CPCOMMIT();
        CPWAIT0();
        __syncthreads();

        float acc[2][4][4];
        #pragma unroll
        for (int mf = 0; mf < 2; mf++)
            #pragma unroll
            for (int nf = 0; nf < 4; nf++)
                #pragma unroll
                for (int e = 0; e < 4; e++) acc[mf][nf][e] = 0.f;

        #pragma unroll 4
        for (int ks = 0; ks < KSP; ks++) {
            uint2 alo[2], ahi[2];
            #pragma unroll
            for (int mf = 0; mf < 2; mf++) {
                int r = wm * 32 + mf * 16 + g;
                alo[mf] = *(const uint2*)(As + ((ks * MT + r) << 3) + 2 * tg);
                ahi[mf] = *(const uint2*)(As + ((ks * MT + r + 8) << 3) + 2 * tg);
            }
            uint2 bf[4];
            #pragma unroll
            for (int nf = 0; nf < 4; nf++) {
                int cc = wn * 32 + nf * 8 + g;
                bf[nf] = *(const uint2*)(Bs + ((ks * NC + cc) << 3) + 2 * tg);
            }
            #pragma unroll
            for (int mf = 0; mf < 2; mf++)
                #pragma unroll
                for (int nf = 0; nf < 4; nf++)
                    mma_bf16(acc[mf][nf], alo[mf].x, ahi[mf].x, alo[mf].y, ahi[mf].y,
                             bf[nf].x, bf[nf].y);
        }

        // phase 1: dt computed ONCE and cached; per-row min -> smem atomicMin
        float dt[2][4][4];
        float rmin[2][2] = {{FLT_MAX, FLT_MAX}, {FLT_MAX, FLT_MAX}};
        #pragma unroll
        for (int mf = 0; mf < 2; mf++)
            #pragma unroll
            for (int nf = 0; nf < 4; nf++) {
                int col0 = wn * 32 + nf * 8 + 2 * tg;
                float c0v = cn[c0 + col0], c1v = cn[c0 + col0 + 1];
                dt[mf][nf][0] = (znr[mf][0] + c0v) - 2.f * acc[mf][nf][0];
                dt[mf][nf][1] = (znr[mf][0] + c1v) - 2.f * acc[mf][nf][1];
                dt[mf][nf][2] = (znr[mf][1] + c0v) - 2.f * acc[mf][nf][2];
                dt[mf][nf][3] = (znr[mf][1] + c1v) - 2.f * acc[mf][nf][3];
                rmin[mf][0] = fminf(rmin[mf][0], fminf(dt[mf][nf][0], dt[mf][nf][1]));
                rmin[mf][1] = fminf(rmin[mf][1], fminf(dt[mf][nf][2], dt[mf][nf][3]));
            }
        #pragma unroll
        for (int mf = 0; mf < 2; mf++)
            #pragma unroll
            for (int rr = 0; rr < 2; rr++) {
                float m = rmin[mf][rr];
                m = fminf(m, __shfl_xor_sync(0xFFFFFFFFu, m, 1));
                m = fminf(m, __shfl_xor_sync(0xFFFFFFFFu, m, 2));
                rmin[mf][rr] = m;
            }
        if (tg == 0) {
            #pragma unroll
            for (int mf = 0; mf < 2; mf++) {
                atomicMin(&smin[wm * 32 + mf * 16 + g],     fmap(rmin[mf][0]));
                atomicMin(&smin[wm * 32 + mf * 16 + g + 8], fmap(rmin[mf][1]));
            }
        }
        // no barrier: stale smem min >= final min keeps admission sound

        // phase 2: windowed admission from cached dt, early-out when no hit
        #pragma unroll
        for (int mf = 0; mf < 2; mf++) {
            int r0 = wm * 32 + mf * 16 + g;
            int r1 = r0 + 8;
            float th0 = fminf(funmap(smin[r0]), rmin[mf][0]) + WINDOW;
            float th1 = fminf(funmap(smin[r1]), rmin[mf][1]) + WINDOW;
            float m0 = FLT_MAX, m1 = FLT_MAX;
            #pragma unroll
            for (int nf = 0; nf < 4; nf++) {
                m0 = fminf(m0, fminf(dt[mf][nf][0], dt[mf][nf][1]));
                m1 = fminf(m1, fminf(dt[mf][nf][2], dt[mf][nf][3]));
            }
            if (m0 <= th0) {
                #pragma unroll
                for (int nf = 0; nf < 4; nf++) {
                    int col0 = wn * 32 + nf * 8 + 2 * tg;
                    if (dt[mf][nf][0] <= th0) {
                        int p = atomicAdd(&scnt[r0], 1);
                        if (p < CAP) sck[r0 * CAP + p] = c0 + col0;
                        else if (p < CAP + EXT) g_candk_ext[(size_t)(n0 + r0) * EXT + (p - CAP)] = c0 + col0;
                    }
                    if (dt[mf][nf][1] <= th0) {
                        int p = atomicAdd(&scnt[r0], 1);
                        if (p < CAP) sck[r0 * CAP + p] = c0 + col0 + 1;
                        else if (p < CAP + EXT) g_candk_ext[(size_t)(n0 + r0) * EXT + (p - CAP)] = c0 + col0 + 1;
                    }
                }
            }
            if (m1 <= th1) {
                #pragma unroll
                for (int nf = 0; nf < 4; nf++) {
                    int col0 = wn * 32 + nf * 8 + 2 * tg;
                    if (dt[mf][nf][2] <= th1) {
                        int p = atomicAdd(&scnt[r1], 1);
                        if (p < CAP) sck[r1 * CAP + p] = c0 + col0;
                        else if (p < CAP + EXT) g_candk_ext[(size_t)(n0 + r1) * EXT + (p - CAP)] = c0 + col0;
                    }
                    if (dt[mf][nf][3] <= th1) {
                        int p = atomicAdd(&scnt[r1], 1);
                        if (p < CAP) sck[r1 * CAP + p] = c0 + col0 + 1;
                        else if (p < CAP + EXT) g_candk_ext[(size_t)(n0 + r1) * EXT + (p - CAP)] = c0 + col0 + 1;
                    }
                }
            }
        }
    }
    __syncthreads();

    if (t < MT) {
        int cnt = scnt[t];
        g_cnum[n0 + t] = (cnt > CAP + EXT) ? 255 : cnt;
        int m = (cnt > CAP) ? CAP : cnt;
        for (int q = 0; q < m; q++)
            g_candk[(size_t)(n0 + t) * CAP + q] = sck[t * CAP + q];
    }
}

// ---------------- kernel 2b: finalize — exact rescore of all candidates ----
__global__ void finalize_kernel(const float* __restrict__ cb) {
    const int t = threadIdx.x, w = t >> 5, l = t & 31;
    const int n = blockIdx.x * 8 + w;

    const int cnum = g_cnum[n];
    if (cnum == 1) {                 // sole admitted candidate IS the argmin
        if (l == 0) g_idx[n] = g_candk[(size_t)n * CAP];
        return;
    }

    const float zn = g_znorm[n];
    const float* zr = g_zt + (size_t)n * DD;
    float zv[8];
    #pragma unroll
    for (int j = 0; j < 8; j++) zv[j] = zr[l + 32 * j];

    float bd = FLT_MAX;
    int   bk = 0x7FFFFFFF;
    const int cmax = (cnum == 255) ? KK : cnum;
    for (int c = 0; c < cmax; c++) {
        int k;
        if (cnum == 255)  k = c;
        else if (c < CAP) k = g_candk[(size_t)n * CAP + c];
        else              k = g_candk_ext[(size_t)n * EXT + (c - CAP)];
        const float* er = cb + (size_t)k * DD;
        float s = 0.f;
        #pragma unroll
        for (int j = 0; j < 8; j++) s = fmaf(zv[j], er[l + 32 * j], s);
        #pragma unroll
        for (int off = 16; off; off >>= 1) s += __shfl_xor_sync(0xFFFFFFFFu, s, off);
        // reference rounding: RN( RN(zn + cn) - 2*dot )
        float dist = __fadd_rn(__fadd_rn(zn, g_cbnorm[k]), -2.0f * s);
        if (dist < bd || (dist == bd && k < bk)) { bd = dist; bk = k; }
    }
    if (l == 0) g_idx[n] = bk;
}

// ---------------- kernel 3: gather + zq_st + indices + loss (float4) ---------
#define GN 128
#define GD 32
#define TP 132     // tile row stride (floats): 16B-aligned float4 rows
__global__ void gather_kernel(const float* __restrict__ z,
                              const float* __restrict__ cb,
                              float* __restrict__ out,
                              int write_extra) {
    __shared__ int   sidx[GN];
    __shared__ float tile[GD * TP];
    __shared__ float red[8];

    const int t   = threadIdx.x;
    const int n0  = blockIdx.x * GN;
    const int d0  = blockIdx.y * GD;
    const int b   = n0 >> 10;
    const int hw0 = n0 & 1023;

    if (t < GN) sidx[t] = g_idx[n0 + t];
    __syncthreads();

    const int w = t >> 5, l = t & 31;
    // gather: warp per n, lanes over 32 consecutive d (coalesced 128B cb reads)
    for (int nn = w; nn < GN; nn += 8)
        tile[l * TP + nn] = cb[sidx[nn] * DD + d0 + l];
    __syncthreads();

    float lsum = 0.f;
    #pragma unroll
    for (int r = 0; r < 4; r++) {              // 4 x 256 threads x float4
        int e  = r * 256 + t;
        int dd = e >> 5;                       // 0..31
        int n  = (e & 31) * 4;
        int d  = d0 + dd;
        float4 q  = *(const float4*)&tile[dd * TP + n];
        int    zi = ((b << 8) + d) * HW + hw0 + n;
        float4 zv = *(const float4*)&z[zi];
        float4 o;
        float dfx = __fsub_rn(q.x, zv.x); o.x = __fadd_rn(zv.x, dfx);
        float dfy = __fsub_rn(q.y, zv.y); o.y = __fadd_rn(zv.y, dfy);
        float dfz = __fsub_rn(q.z, zv.z); o.z = __fadd_rn(zv.z, dfz);
        float dfw = __fsub_rn(q.w, zv.w); o.w = __fadd_rn(zv.w, dfw);
        *(float4*)&out[zi] = o;                // zq_st = zp + RN(zq - zp), bitwise
        lsum = fmaf(dfx, dfx, lsum);
        lsum = fmaf(dfy, dfy, lsum);
        lsum = fmaf(dfz, dfz, lsum);
        lsum = fmaf(dfw, dfw, lsum);
    }

    #pragma unroll
    for (int off = 16; off; off >>= 1)
        lsum += __shfl_xor_sync(0xFFFFFFFFu, lsum, off);
    if (l == 0) red[w] = lsum;
    __syncthreads();
    if (t == 0) {
        float s = 0.f;
        #pragma unroll
        for (int i = 0; i < 8; i++) s += red[i];
        g_partial[blockIdx.y * gridDim.x + blockIdx.x] = s;
    }
    if (write_extra && blockIdx.y == 0 && t < GN)
        out[IDX_OFF + n0 + t] = (float)sidx[t];
}

// ---------------- kernel 4: finalize loss ----------------
__global__ void loss_kernel(float* __restrict__ out) {
    __shared__ float red[8];
    int t = threadIdx.x;
    float s = 0.f;
    #pragma unroll
    for (int i = 0; i < 8; i++)
        s += g_partial[t * 8 + i];
    #pragma unroll
    for (int off = 16; off; off >>= 1)
        s += __shfl_xor_sync(0xFFFFFFFFu, s, off);
    if ((t & 31) == 0) red[t >> 5] = s;
    __syncthreads();
    if (t == 0) {
        double tot = 0.0;
        #pragma unroll
        for (int i = 0; i < 8; i++) tot += (double)red[i];
        out[LOSS_OFF] = (float)(2.0 * tot / (double)ZQ_SIZE);
    }
}

// ---------------- launch ----------------
extern "C" void kernel_launch(void* const* d_in, const int* in_sizes, int n_in,
                              void* d_out, int out_size) {
    const float* z  = (const float*)d_in[0];
    const float* cb = (const float*)d_in[1];
    float* out = (float*)d_out;

    int write_extra = (out_size >= LOSS_OFF + 1) ? 1 : 0;

    z_fused_kernel<<<NN / 32, 256>>>(z);
    cbnorm_cbw_kernel<<<KK / 32, 32>>>(cb);

    // smem: As 64K + Bs 32K + cn 4K + smin/scnt 1K + sck 8K = 109 KB
    size_t smem = (16384 + 8192 + KK + 128 + 128 + 128 * CAP) * 4;
    cudaFuncSetAttribute(mma_cand_kernel,
                         cudaFuncAttributeMaxDynamicSharedMemorySize, (int)smem);
    mma_cand_kernel<<<NN / MT, 256, smem>>>();

    finalize_kernel<<<NN / 8, 256>>>(cb);

    gather_kernel<<<dim3(NN / GN, DD / GD), 256>>>(z, cb, out, write_extra);

    if (write_extra)
        loss_kernel<<<1, 256>>>(out);
}